// round 1
// baseline (speedup 1.0000x reference)
#include <cuda_runtime.h>
#include <cuda_bf16.h>
#include <math.h>

// Shapes (fixed by the problem)
#define BATCH 16
#define CHAN  256
#define HH_   224
#define WW_   224
#define PLANE_ELEMS (HH_ * WW_)          // 50176 floats per (b,c) plane
#define PLANE_V4    (PLANE_ELEMS / 4)    // 12544 float4
#define NPLANES     (BATCH * CHAN)       // 4096
#define W4_PER_ROW  (WW_ / 4)            // 56 float4 per row
#define SUB_ELEMS   (112 * 112)          // 12544 elements per parity grid

// Scratch (device globals — no allocation allowed)
__device__ float g_sums[NPLANES * 4];    // per-plane parity sums: [he_we, ho_we, he_wo, ho_wo]
__device__ float g_scale[NPLANES];       // final per-(b,c) sigmoid scale

// ---------------------------------------------------------------------------
// Kernel 1: per-plane parity sums. One block per (b,c) plane, 256 threads,
// float4 loads (49 per thread). Within a float4 at row h: lanes .x/.z are
// even-w, .y/.w are odd-w.
// ---------------------------------------------------------------------------
__global__ __launch_bounds__(256) void parity_sum_kernel(const float* __restrict__ x) {
    const int plane = blockIdx.x;
    const int t = threadIdx.x;
    const float4* __restrict__ p = (const float4*)(x + (size_t)plane * PLANE_ELEMS);

    float s_he_we = 0.f, s_ho_we = 0.f, s_he_wo = 0.f, s_ho_wo = 0.f;

    #pragma unroll 7
    for (int i = t; i < PLANE_V4; i += 256) {
        float4 v = p[i];
        int h = i / W4_PER_ROW;          // row index
        float ev = v.x + v.z;            // even-w
        float od = v.y + v.w;            // odd-w
        if (h & 1) { s_ho_we += ev; s_ho_wo += od; }
        else       { s_he_we += ev; s_he_wo += od; }
    }

    // warp reduce 4 values
    #pragma unroll
    for (int off = 16; off > 0; off >>= 1) {
        s_he_we += __shfl_down_sync(0xffffffffu, s_he_we, off);
        s_ho_we += __shfl_down_sync(0xffffffffu, s_ho_we, off);
        s_he_wo += __shfl_down_sync(0xffffffffu, s_he_wo, off);
        s_ho_wo += __shfl_down_sync(0xffffffffu, s_ho_wo, off);
    }

    __shared__ float red[8][4];
    int lane = t & 31, wid = t >> 5;
    if (lane == 0) {
        red[wid][0] = s_he_we; red[wid][1] = s_ho_we;
        red[wid][2] = s_he_wo; red[wid][3] = s_ho_wo;
    }
    __syncthreads();
    if (t < 4) {
        float acc = 0.f;
        #pragma unroll
        for (int w = 0; w < 8; w++) acc += red[w][t];
        g_sums[plane * 4 + t] = acc;
    }
}

// ---------------------------------------------------------------------------
// Kernel 2: per-batch head. 16 blocks x 256 threads.
//   means -> band stats ori_y[4][256] -> logits (w_enc) -> argmax -> Q ->
//   y = sum relu(ori - Q) -> h = relu(y @ w1^T) -> s = sigmoid(h @ w2^T)
// ---------------------------------------------------------------------------
__global__ __launch_bounds__(256) void head_kernel(const float* __restrict__ w1,
                                                   const float* __restrict__ w2,
                                                   const float* __restrict__ w_enc,
                                                   const float* __restrict__ b_enc) {
    const int b = blockIdx.x;
    const int t = threadIdx.x;   // = channel index

    __shared__ float ori[4][CHAN];
    __shared__ float ysh[CHAN];
    __shared__ float hsh[CHAN / 2];
    __shared__ float red[8][4];
    __shared__ int s_top;

    const float inv = 0.5f / (float)SUB_ELEMS;  // the 0.5 factor folded into the mean
    const int plane = b * CHAN + t;
    float m1 = g_sums[plane * 4 + 0] * inv;  // even h, even w  (x1)
    float m2 = g_sums[plane * 4 + 1] * inv;  // odd  h, even w  (x2)
    float m3 = g_sums[plane * 4 + 2] * inv;  // even h, odd  w  (x3)
    float m4 = g_sums[plane * 4 + 3] * inv;  // odd  h, odd  w  (x4)

    float LL =  m1 + m2 + m3 + m4;
    float HL = -m1 - m2 + m3 + m4;
    float LH = -m1 + m2 - m3 + m4;
    float HHb = m1 - m2 - m3 + m4;
    ori[0][t] = LL; ori[1][t] = HL; ori[2][t] = LH; ori[3][t] = HHb;

    // logits for argmax (sigmoid is monotonic, b_enc shared -> skip both)
    float we = w_enc[t];
    float p0 = LL * we, p1 = HL * we, p2 = LH * we, p3 = HHb * we;
    #pragma unroll
    for (int off = 16; off > 0; off >>= 1) {
        p0 += __shfl_down_sync(0xffffffffu, p0, off);
        p1 += __shfl_down_sync(0xffffffffu, p1, off);
        p2 += __shfl_down_sync(0xffffffffu, p2, off);
        p3 += __shfl_down_sync(0xffffffffu, p3, off);
    }
    int lane = t & 31, wid = t >> 5;
    if (lane == 0) { red[wid][0] = p0; red[wid][1] = p1; red[wid][2] = p2; red[wid][3] = p3; }
    __syncthreads();
    if (t == 0) {
        float l0 = 0.f, l1 = 0.f, l2 = 0.f, l3 = 0.f;
        #pragma unroll
        for (int w = 0; w < 8; w++) { l0 += red[w][0]; l1 += red[w][1]; l2 += red[w][2]; l3 += red[w][3]; }
        int best = 0; float bv = l0;
        if (l1 > bv) { bv = l1; best = 1; }
        if (l2 > bv) { bv = l2; best = 2; }
        if (l3 > bv) { bv = l3; best = 3; }
        s_top = best;
    }
    __syncthreads();

    float Q = ori[s_top][t];
    float yy = fmaxf(LL - Q, 0.f) + fmaxf(HL - Q, 0.f) + fmaxf(LH - Q, 0.f) + fmaxf(HHb - Q, 0.f);
    ysh[t] = yy;
    __syncthreads();

    // h = relu(y @ w1^T), w1: [128, 256]
    if (t < CHAN / 2) {
        const float* __restrict__ row = w1 + (size_t)t * CHAN;
        float acc = 0.f;
        #pragma unroll 8
        for (int c = 0; c < CHAN; c++) acc = fmaf(ysh[c], row[c], acc);
        hsh[t] = fmaxf(acc, 0.f);
    }
    __syncthreads();

    // s = sigmoid(h @ w2^T), w2: [256, 128]
    {
        const float* __restrict__ row = w2 + (size_t)t * (CHAN / 2);
        float acc = 0.f;
        #pragma unroll 8
        for (int j = 0; j < CHAN / 2; j++) acc = fmaf(hsh[j], row[j], acc);
        g_scale[plane] = 1.0f / (1.0f + __expf(-acc));
    }
}

// ---------------------------------------------------------------------------
// Kernel 3: out = x * s[plane], float4 vectorized.
// 49 blocks per plane (12544 float4 / 256 threads), 4096*49 = 200704 blocks.
// ---------------------------------------------------------------------------
__global__ __launch_bounds__(256) void scale_kernel(const float* __restrict__ x,
                                                    float* __restrict__ out) {
    const int plane = blockIdx.x / 49;              // constant divide -> IMAD
    const size_t i = (size_t)blockIdx.x * 256 + threadIdx.x;  // float4 index
    const float s = g_scale[plane];
    float4 v = ((const float4*)x)[i];
    v.x *= s; v.y *= s; v.z *= s; v.w *= s;
    ((float4*)out)[i] = v;
}

// ---------------------------------------------------------------------------
extern "C" void kernel_launch(void* const* d_in, const int* in_sizes, int n_in,
                              void* d_out, int out_size) {
    const float* x     = (const float*)d_in[0];  // [16,256,224,224]
    const float* w1    = (const float*)d_in[1];  // [128,256]
    const float* w2    = (const float*)d_in[2];  // [256,128]
    const float* w_enc = (const float*)d_in[3];  // [1,256]
    const float* b_enc = (const float*)d_in[4];  // [1]
    float* out = (float*)d_out;

    parity_sum_kernel<<<NPLANES, 256>>>(x);
    head_kernel<<<BATCH, 256>>>(w1, w2, w_enc, b_enc);
    scale_kernel<<<NPLANES * (PLANE_V4 / 256), 256>>>(x, out);
}

// round 2
// speedup vs baseline: 1.0119x; 1.0119x over previous
#include <cuda_runtime.h>
#include <cuda_bf16.h>
#include <math.h>

// Shapes (fixed by the problem)
#define BATCH 16
#define CHAN  256
#define HH_   224
#define WW_   224
#define PLANE_ELEMS (HH_ * WW_)          // 50176 floats per (b,c) plane
#define PLANE_V4    (PLANE_ELEMS / 4)    // 12544 float4
#define NPLANES     (BATCH * CHAN)       // 4096
#define W4_PER_ROW  (WW_ / 4)            // 56 float4 per row
#define SUB_ELEMS   (112 * 112)          // 12544 elements per parity grid

// scale kernel tiling: 7 blocks per plane, 7 float4 per thread
#define SBLK_PER_PLANE 7
#define V4_PER_THREAD  7
#define SBLK_V4 (256 * V4_PER_THREAD)    // 1792 float4 per block

// Scratch (device globals — no allocation allowed)
__device__ float g_sums[NPLANES * 4];    // per-plane parity sums
__device__ float g_scale[NPLANES];       // final per-(b,c) sigmoid scale

// ---------------------------------------------------------------------------
// Kernel 1: per-plane parity sums. One block per (b,c) plane, 256 threads,
// float4 streaming loads (49 per thread).
// ---------------------------------------------------------------------------
__global__ __launch_bounds__(256) void parity_sum_kernel(const float* __restrict__ x) {
    const int plane = blockIdx.x;
    const int t = threadIdx.x;
    const float4* __restrict__ p = (const float4*)(x + (size_t)plane * PLANE_ELEMS);

    float s_he_we = 0.f, s_ho_we = 0.f, s_he_wo = 0.f, s_ho_wo = 0.f;

    #pragma unroll 7
    for (int i = t; i < PLANE_V4; i += 256) {
        float4 v = __ldcs(&p[i]);
        int h = i / W4_PER_ROW;          // row index
        float ev = v.x + v.z;            // even-w
        float od = v.y + v.w;            // odd-w
        if (h & 1) { s_ho_we += ev; s_ho_wo += od; }
        else       { s_he_we += ev; s_he_wo += od; }
    }

    // warp reduce 4 values
    #pragma unroll
    for (int off = 16; off > 0; off >>= 1) {
        s_he_we += __shfl_down_sync(0xffffffffu, s_he_we, off);
        s_ho_we += __shfl_down_sync(0xffffffffu, s_ho_we, off);
        s_he_wo += __shfl_down_sync(0xffffffffu, s_he_wo, off);
        s_ho_wo += __shfl_down_sync(0xffffffffu, s_ho_wo, off);
    }

    __shared__ float red[8][4];
    int lane = t & 31, wid = t >> 5;
    if (lane == 0) {
        red[wid][0] = s_he_we; red[wid][1] = s_ho_we;
        red[wid][2] = s_he_wo; red[wid][3] = s_ho_wo;
    }
    __syncthreads();
    if (t < 4) {
        float acc = 0.f;
        #pragma unroll
        for (int w = 0; w < 8; w++) acc += red[w][t];
        g_sums[plane * 4 + t] = acc;
    }
}

// ---------------------------------------------------------------------------
// Kernel 2: per-batch head. 16 blocks x 256 threads.
// ---------------------------------------------------------------------------
__global__ __launch_bounds__(256) void head_kernel(const float* __restrict__ w1,
                                                   const float* __restrict__ w2,
                                                   const float* __restrict__ w_enc,
                                                   const float* __restrict__ b_enc) {
    const int b = blockIdx.x;
    const int t = threadIdx.x;   // = channel index

    __shared__ float ori[4][CHAN];
    __shared__ float ysh[CHAN];
    __shared__ float hsh[CHAN / 2];
    __shared__ float red[8][4];
    __shared__ int s_top;

    const float inv = 0.5f / (float)SUB_ELEMS;  // 0.5 folded into the mean
    const int plane = b * CHAN + t;
    float m1 = g_sums[plane * 4 + 0] * inv;  // even h, even w  (x1)
    float m2 = g_sums[plane * 4 + 1] * inv;  // odd  h, even w  (x2)
    float m3 = g_sums[plane * 4 + 2] * inv;  // even h, odd  w  (x3)
    float m4 = g_sums[plane * 4 + 3] * inv;  // odd  h, odd  w  (x4)

    float LL =  m1 + m2 + m3 + m4;
    float HL = -m1 - m2 + m3 + m4;
    float LH = -m1 + m2 - m3 + m4;
    float HHb = m1 - m2 - m3 + m4;
    ori[0][t] = LL; ori[1][t] = HL; ori[2][t] = LH; ori[3][t] = HHb;

    // logits for argmax (sigmoid monotonic, b_enc shared -> skip both)
    float we = w_enc[t];
    float p0 = LL * we, p1 = HL * we, p2 = LH * we, p3 = HHb * we;
    #pragma unroll
    for (int off = 16; off > 0; off >>= 1) {
        p0 += __shfl_down_sync(0xffffffffu, p0, off);
        p1 += __shfl_down_sync(0xffffffffu, p1, off);
        p2 += __shfl_down_sync(0xffffffffu, p2, off);
        p3 += __shfl_down_sync(0xffffffffu, p3, off);
    }
    int lane = t & 31, wid = t >> 5;
    if (lane == 0) { red[wid][0] = p0; red[wid][1] = p1; red[wid][2] = p2; red[wid][3] = p3; }
    __syncthreads();
    if (t == 0) {
        float l0 = 0.f, l1 = 0.f, l2 = 0.f, l3 = 0.f;
        #pragma unroll
        for (int w = 0; w < 8; w++) { l0 += red[w][0]; l1 += red[w][1]; l2 += red[w][2]; l3 += red[w][3]; }
        int best = 0; float bv = l0;
        if (l1 > bv) { bv = l1; best = 1; }
        if (l2 > bv) { bv = l2; best = 2; }
        if (l3 > bv) { bv = l3; best = 3; }
        s_top = best;
    }
    __syncthreads();

    float Q = ori[s_top][t];
    float yy = fmaxf(LL - Q, 0.f) + fmaxf(HL - Q, 0.f) + fmaxf(LH - Q, 0.f) + fmaxf(HHb - Q, 0.f);
    ysh[t] = yy;
    __syncthreads();

    // h = relu(y @ w1^T), w1: [128, 256]
    if (t < CHAN / 2) {
        const float* __restrict__ row = w1 + (size_t)t * CHAN;
        float acc = 0.f;
        #pragma unroll 8
        for (int c = 0; c < CHAN; c++) acc = fmaf(ysh[c], row[c], acc);
        hsh[t] = fmaxf(acc, 0.f);
    }
    __syncthreads();

    // s = sigmoid(h @ w2^T), w2: [256, 128]
    {
        const float* __restrict__ row = w2 + (size_t)t * (CHAN / 2);
        float acc = 0.f;
        #pragma unroll 8
        for (int j = 0; j < CHAN / 2; j++) acc = fmaf(hsh[j], row[j], acc);
        g_scale[plane] = 1.0f / (1.0f + __expf(-acc));
    }
}

// ---------------------------------------------------------------------------
// Kernel 3: out = x * s[plane]. 7 blocks per plane, 7 float4 per thread,
// all loads issued before stores (MLP_p1 = 7), streaming hints.
// ---------------------------------------------------------------------------
__global__ __launch_bounds__(256) void scale_kernel(const float* __restrict__ x,
                                                    float* __restrict__ out) {
    const int plane = blockIdx.x / SBLK_PER_PLANE;
    const float s = g_scale[plane];
    const size_t base = (size_t)blockIdx.x * SBLK_V4 + threadIdx.x;

    const float4* __restrict__ src = (const float4*)x;
    float4* __restrict__ dst = (float4*)out;

    float4 v[V4_PER_THREAD];
    #pragma unroll
    for (int k = 0; k < V4_PER_THREAD; k++)
        v[k] = __ldcs(&src[base + (size_t)k * 256]);
    #pragma unroll
    for (int k = 0; k < V4_PER_THREAD; k++) {
        v[k].x *= s; v[k].y *= s; v[k].z *= s; v[k].w *= s;
        __stcs(&dst[base + (size_t)k * 256], v[k]);
    }
}

// ---------------------------------------------------------------------------
extern "C" void kernel_launch(void* const* d_in, const int* in_sizes, int n_in,
                              void* d_out, int out_size) {
    const float* x     = (const float*)d_in[0];  // [16,256,224,224]
    const float* w1    = (const float*)d_in[1];  // [128,256]
    const float* w2    = (const float*)d_in[2];  // [256,128]
    const float* w_enc = (const float*)d_in[3];  // [1,256]
    const float* b_enc = (const float*)d_in[4];  // [1]
    float* out = (float*)d_out;

    parity_sum_kernel<<<NPLANES, 256>>>(x);
    head_kernel<<<BATCH, 256>>>(w1, w2, w_enc, b_enc);
    scale_kernel<<<NPLANES * SBLK_PER_PLANE, 256>>>(x, out);
}

// round 3
// speedup vs baseline: 1.0143x; 1.0024x over previous
#include <cuda_runtime.h>
#include <cuda_bf16.h>
#include <math.h>

// Shapes (fixed by the problem)
#define BATCH 16
#define CHAN  256
#define HH_   224
#define WW_   224
#define PLANE_ELEMS (HH_ * WW_)          // 50176 floats per (b,c) plane
#define PLANE_V4    (PLANE_ELEMS / 4)    // 12544 float4
#define NPLANES     (BATCH * CHAN)       // 4096
#define W4_PER_ROW  (WW_ / 4)            // 56 float4 per row
#define SUB_ELEMS   (112 * 112)          // 12544 elements per parity grid

// scale kernel tiling: 7 blocks per plane, 7 float4 per thread
#define SBLK_PER_PLANE 7
#define V4_PER_THREAD  7
#define SBLK_V4 (256 * V4_PER_THREAD)    // 1792 float4 per block
#define NSBLK (NPLANES * SBLK_PER_PLANE) // 28672 blocks

// Scratch (device globals — no allocation allowed)
__device__ float g_sums[NPLANES * 4];    // per-plane parity sums
__device__ float g_scale[NPLANES];       // final per-(b,c) sigmoid scale

// ---------------------------------------------------------------------------
// Kernel 1: per-plane parity sums. One block per (b,c) plane, 256 threads,
// float4 loads (49 per thread). DEFAULT cache policy so the tail of x stays
// resident in L2 for pass 3's reverse-order reads.
// ---------------------------------------------------------------------------
__global__ __launch_bounds__(256) void parity_sum_kernel(const float* __restrict__ x) {
    const int plane = blockIdx.x;
    const int t = threadIdx.x;
    const float4* __restrict__ p = (const float4*)(x + (size_t)plane * PLANE_ELEMS);

    float s_he_we = 0.f, s_ho_we = 0.f, s_he_wo = 0.f, s_ho_wo = 0.f;

    #pragma unroll 7
    for (int i = t; i < PLANE_V4; i += 256) {
        float4 v = p[i];
        int h = i / W4_PER_ROW;          // row index
        float ev = v.x + v.z;            // even-w
        float od = v.y + v.w;            // odd-w
        if (h & 1) { s_ho_we += ev; s_ho_wo += od; }
        else       { s_he_we += ev; s_he_wo += od; }
    }

    // warp reduce 4 values
    #pragma unroll
    for (int off = 16; off > 0; off >>= 1) {
        s_he_we += __shfl_down_sync(0xffffffffu, s_he_we, off);
        s_ho_we += __shfl_down_sync(0xffffffffu, s_ho_we, off);
        s_he_wo += __shfl_down_sync(0xffffffffu, s_he_wo, off);
        s_ho_wo += __shfl_down_sync(0xffffffffu, s_ho_wo, off);
    }

    __shared__ float red[8][4];
    int lane = t & 31, wid = t >> 5;
    if (lane == 0) {
        red[wid][0] = s_he_we; red[wid][1] = s_ho_we;
        red[wid][2] = s_he_wo; red[wid][3] = s_ho_wo;
    }
    __syncthreads();
    if (t < 4) {
        float acc = 0.f;
        #pragma unroll
        for (int w = 0; w < 8; w++) acc += red[w][t];
        g_sums[plane * 4 + t] = acc;
    }
}

// ---------------------------------------------------------------------------
// Kernel 2: per-batch head. 16 blocks x 256 threads.
// ---------------------------------------------------------------------------
__global__ __launch_bounds__(256) void head_kernel(const float* __restrict__ w1,
                                                   const float* __restrict__ w2,
                                                   const float* __restrict__ w_enc,
                                                   const float* __restrict__ b_enc) {
    const int b = blockIdx.x;
    const int t = threadIdx.x;   // = channel index

    __shared__ float ori[4][CHAN];
    __shared__ float ysh[CHAN];
    __shared__ float hsh[CHAN / 2];
    __shared__ float red[8][4];
    __shared__ int s_top;

    const float inv = 0.5f / (float)SUB_ELEMS;  // 0.5 folded into the mean
    const int plane = b * CHAN + t;
    float m1 = g_sums[plane * 4 + 0] * inv;  // even h, even w  (x1)
    float m2 = g_sums[plane * 4 + 1] * inv;  // odd  h, even w  (x2)
    float m3 = g_sums[plane * 4 + 2] * inv;  // even h, odd  w  (x3)
    float m4 = g_sums[plane * 4 + 3] * inv;  // odd  h, odd  w  (x4)

    float LL =  m1 + m2 + m3 + m4;
    float HL = -m1 - m2 + m3 + m4;
    float LH = -m1 + m2 - m3 + m4;
    float HHb = m1 - m2 - m3 + m4;
    ori[0][t] = LL; ori[1][t] = HL; ori[2][t] = LH; ori[3][t] = HHb;

    // logits for argmax (sigmoid monotonic, b_enc shared -> skip both)
    float we = w_enc[t];
    float p0 = LL * we, p1 = HL * we, p2 = LH * we, p3 = HHb * we;
    #pragma unroll
    for (int off = 16; off > 0; off >>= 1) {
        p0 += __shfl_down_sync(0xffffffffu, p0, off);
        p1 += __shfl_down_sync(0xffffffffu, p1, off);
        p2 += __shfl_down_sync(0xffffffffu, p2, off);
        p3 += __shfl_down_sync(0xffffffffu, p3, off);
    }
    int lane = t & 31, wid = t >> 5;
    if (lane == 0) { red[wid][0] = p0; red[wid][1] = p1; red[wid][2] = p2; red[wid][3] = p3; }
    __syncthreads();
    if (t == 0) {
        float l0 = 0.f, l1 = 0.f, l2 = 0.f, l3 = 0.f;
        #pragma unroll
        for (int w = 0; w < 8; w++) { l0 += red[w][0]; l1 += red[w][1]; l2 += red[w][2]; l3 += red[w][3]; }
        int best = 0; float bv = l0;
        if (l1 > bv) { bv = l1; best = 1; }
        if (l2 > bv) { bv = l2; best = 2; }
        if (l3 > bv) { bv = l3; best = 3; }
        s_top = best;
    }
    __syncthreads();

    float Q = ori[s_top][t];
    float yy = fmaxf(LL - Q, 0.f) + fmaxf(HL - Q, 0.f) + fmaxf(LH - Q, 0.f) + fmaxf(HHb - Q, 0.f);
    ysh[t] = yy;
    __syncthreads();

    // h = relu(y @ w1^T), w1: [128, 256]
    if (t < CHAN / 2) {
        const float* __restrict__ row = w1 + (size_t)t * CHAN;
        float acc = 0.f;
        #pragma unroll 8
        for (int c = 0; c < CHAN; c++) acc = fmaf(ysh[c], row[c], acc);
        hsh[t] = fmaxf(acc, 0.f);
    }
    __syncthreads();

    // s = sigmoid(h @ w2^T), w2: [256, 128]
    {
        const float* __restrict__ row = w2 + (size_t)t * (CHAN / 2);
        float acc = 0.f;
        #pragma unroll 8
        for (int j = 0; j < CHAN / 2; j++) acc = fmaf(hsh[j], row[j], acc);
        g_scale[plane] = 1.0f / (1.0f + __expf(-acc));
    }
}

// ---------------------------------------------------------------------------
// Kernel 3: out = x * s[plane], REVERSE plane order so the first blocks read
// the tail of x that pass 1 left resident in L2. Default-policy loads (hit
// L2), evict-first stores (don't displace the read tail).
// ---------------------------------------------------------------------------
__global__ __launch_bounds__(256) void scale_kernel(const float* __restrict__ x,
                                                    float* __restrict__ out) {
    const int rev = (NSBLK - 1) - (int)blockIdx.x;     // reversed block id
    const int plane = rev / SBLK_PER_PLANE;
    const float s = g_scale[plane];
    const size_t base = (size_t)rev * SBLK_V4 + threadIdx.x;

    const float4* __restrict__ src = (const float4*)x;
    float4* __restrict__ dst = (float4*)out;

    float4 v[V4_PER_THREAD];
    #pragma unroll
    for (int k = 0; k < V4_PER_THREAD; k++)
        v[k] = src[base + (size_t)k * 256];
    #pragma unroll
    for (int k = 0; k < V4_PER_THREAD; k++) {
        v[k].x *= s; v[k].y *= s; v[k].z *= s; v[k].w *= s;
        __stcs(&dst[base + (size_t)k * 256], v[k]);
    }
}

// ---------------------------------------------------------------------------
extern "C" void kernel_launch(void* const* d_in, const int* in_sizes, int n_in,
                              void* d_out, int out_size) {
    const float* x     = (const float*)d_in[0];  // [16,256,224,224]
    const float* w1    = (const float*)d_in[1];  // [128,256]
    const float* w2    = (const float*)d_in[2];  // [256,128]
    const float* w_enc = (const float*)d_in[3];  // [1,256]
    const float* b_enc = (const float*)d_in[4];  // [1]
    float* out = (float*)d_out;

    parity_sum_kernel<<<NPLANES, 256>>>(x);
    head_kernel<<<BATCH, 256>>>(w1, w2, w_enc, b_enc);
    scale_kernel<<<NSBLK, 256>>>(x, out);
}